// round 2
// baseline (speedup 1.0000x reference)
#include <cuda_runtime.h>
#include <cstdint>

#define NN 50000
#define EE 800000
#define HD 128
#define ODIM 40

// ---------------- scratch (static __device__, no allocations) ----------------
__device__ __align__(128) float g_h[NN * HD];     // post-GEMM features
__device__ __align__(128) float g_a[NN * HD];     // post-aggregation activations
__device__ __align__(128) float g_h3[NN * ODIM];  // layer-3 post-GEMM (40 wide)
__device__ float g_dinv[NN];
__device__ int   g_cnt[NN];       // in-degree (edges only, self-loop added in dinv)
__device__ int   g_rowptr[NN];    // CSR row starts (exclusive scan of g_cnt)
__device__ int   g_cursor[NN];    // fill cursors
__device__ int   g_csrc[EE];      // CSR src indices
__device__ float g_cnorm[EE];     // CSR edge norms dinv[s]*dinv[d]
__device__ int   g_bsum[64];
__device__ int   g_is64;

// ---------------- edge-index dtype detection ----------------
// jnp.int64 silently becomes int32 when jax x64 is off. Values are in [0,N) so
// for int64 every odd 32-bit word (high half) is exactly 0. For int32, 512
// random values in [0,50000) are all-zero with probability ~0.
__global__ void k_detect(const void* ei) {
    __shared__ int any;
    if (threadIdx.x == 0) any = 0;
    __syncthreads();
    const int* p = (const int*)ei;
    for (int i = threadIdx.x; i < 512; i += blockDim.x)
        if (p[2 * i + 1] != 0) any = 1;
    __syncthreads();
    if (threadIdx.x == 0) g_is64 = any ? 0 : 1;
}

__device__ __forceinline__ int load_edge(const void* ei, int idx) {
    if (g_is64) return (int)((const long long*)ei)[idx];
    return ((const int*)ei)[idx];
}

// ---------------- CSR build ----------------
__global__ void k_zero_cnt(int n) {
    int i = blockIdx.x * blockDim.x + threadIdx.x;
    if (i < n) g_cnt[i] = 0;
}

__global__ void k_hist(const void* ei, int E) {
    int e = blockIdx.x * blockDim.x + threadIdx.x;
    if (e >= E) return;
    int d = load_edge(ei, E + e);
    atomicAdd(&g_cnt[d], 1);
}

__global__ void k_dinv(int n) {
    int i = blockIdx.x * blockDim.x + threadIdx.x;
    if (i < n) g_dinv[i] = rsqrtf((float)(g_cnt[i] + 1));  // +1 self-loop
}

// block-wise exclusive scan of g_cnt into g_rowptr, block sums into g_bsum
__global__ void k_scanA(int n) {
    __shared__ int sh[1024];
    int tid = threadIdx.x;
    int i = blockIdx.x * 1024 + tid;
    int v = (i < n) ? g_cnt[i] : 0;
    sh[tid] = v;
    __syncthreads();
    for (int off = 1; off < 1024; off <<= 1) {
        int t = (tid >= off) ? sh[tid - off] : 0;
        __syncthreads();
        sh[tid] += t;
        __syncthreads();
    }
    if (i < n) g_rowptr[i] = sh[tid] - v;
    if (tid == 1023) g_bsum[blockIdx.x] = sh[tid];
}

__global__ void k_scanB(int nb) {
    __shared__ int sh[64];
    int tid = threadIdx.x;  // blockDim = 64
    int v = (tid < nb) ? g_bsum[tid] : 0;
    sh[tid] = v;
    __syncthreads();
    for (int off = 1; off < 64; off <<= 1) {
        int t = (tid >= off) ? sh[tid - off] : 0;
        __syncthreads();
        sh[tid] += t;
        __syncthreads();
    }
    if (tid < nb) g_bsum[tid] = sh[tid] - v;  // exclusive
}

__global__ void k_scanC(int n) {
    int i = blockIdx.x * blockDim.x + threadIdx.x;
    if (i >= n) return;
    int v = g_rowptr[i] + g_bsum[i >> 10];
    g_rowptr[i] = v;
    g_cursor[i] = v;
}

__global__ void k_fill(const void* ei, int E) {
    int e = blockIdx.x * blockDim.x + threadIdx.x;
    if (e >= E) return;
    int s = load_edge(ei, e);
    int d = load_edge(ei, E + e);
    int pos = atomicAdd(&g_cursor[d], 1);
    g_csrc[pos] = s;
    g_cnorm[pos] = g_dinv[s] * g_dinv[d];
}

// ---------------- GEMM: [n,128] @ [128,128] ----------------
// 64-row x 128-col block tile, 256 threads, 4x8 micro-tile, K chunked by 32.
__global__ void __launch_bounds__(256) k_gemm128(
    const float* __restrict__ X, const float* __restrict__ W,
    float* __restrict__ O, int n)
{
    __shared__ float xs[64][36];   // [row][k], padded
    __shared__ float ws[32][132];  // [k][col], padded

    int tid = threadIdx.x;
    int row0 = blockIdx.x * 64;
    int cx = tid & 15;   // 16 col groups
    int ry = tid >> 4;   // 16 row groups
    int r0 = ry * 4;
    int c1 = cx * 4;
    int c2 = cx * 4 + 64;

    float acc[4][8];
#pragma unroll
    for (int r = 0; r < 4; r++)
#pragma unroll
        for (int j = 0; j < 8; j++) acc[r][j] = 0.f;

    int lrow = tid >> 3;        // 0..31
    int lkq  = (tid & 7) * 4;   // k quad offset
    int wc4  = (tid & 31) * 4;  // col
    int wkr  = tid >> 5;        // 0..7

    for (int k0 = 0; k0 < 128; k0 += 32) {
        // stage x tile [64][32]
#pragma unroll
        for (int rep = 0; rep < 2; rep++) {
            int row = row0 + lrow + rep * 32;
            float4 v = (row < n) ? *(const float4*)&X[(size_t)row * 128 + k0 + lkq]
                                 : make_float4(0.f, 0.f, 0.f, 0.f);
            *(float4*)&xs[lrow + rep * 32][lkq] = v;
        }
        // stage W chunk [32][128]
#pragma unroll
        for (int rep = 0; rep < 4; rep++) {
            int k = wkr + rep * 8;
            float4 v = *(const float4*)&W[(size_t)(k0 + k) * 128 + wc4];
            *(float4*)&ws[k][wc4] = v;
        }
        __syncthreads();

#pragma unroll 8
        for (int k = 0; k < 32; k++) {
            float xv[4];
#pragma unroll
            for (int r = 0; r < 4; r++) xv[r] = xs[r0 + r][k];
            float4 wa = *(const float4*)&ws[k][c1];
            float4 wb = *(const float4*)&ws[k][c2];
#pragma unroll
            for (int r = 0; r < 4; r++) {
                acc[r][0] += xv[r] * wa.x;
                acc[r][1] += xv[r] * wa.y;
                acc[r][2] += xv[r] * wa.z;
                acc[r][3] += xv[r] * wa.w;
                acc[r][4] += xv[r] * wb.x;
                acc[r][5] += xv[r] * wb.y;
                acc[r][6] += xv[r] * wb.z;
                acc[r][7] += xv[r] * wb.w;
            }
        }
        __syncthreads();
    }

#pragma unroll
    for (int r = 0; r < 4; r++) {
        int row = row0 + r0 + r;
        if (row < n) {
            *(float4*)&O[(size_t)row * 128 + c1] =
                make_float4(acc[r][0], acc[r][1], acc[r][2], acc[r][3]);
            *(float4*)&O[(size_t)row * 128 + c2] =
                make_float4(acc[r][4], acc[r][5], acc[r][6], acc[r][7]);
        }
    }
}

// ---------------- GEMM: [n,128] @ [128,40] ----------------
__global__ void __launch_bounds__(256) k_gemm40(
    const float* __restrict__ X, const float* __restrict__ W2,
    float* __restrict__ O, int n)
{
    __shared__ float ws[128 * ODIM];  // 20 KB
    __shared__ float xs[8][128];
    for (int i = threadIdx.x; i < 128 * ODIM; i += 256) ws[i] = W2[i];
    __syncthreads();

    int wim = threadIdx.x >> 5;
    int lane = threadIdx.x & 31;
    int row = blockIdx.x * 8 + wim;
    if (row >= n) return;

    *(float4*)&xs[wim][lane * 4] = *(const float4*)&X[(size_t)row * 128 + lane * 4];
    __syncwarp();

    float a1 = 0.f, a2 = 0.f;
    int c2 = 32 + lane;
#pragma unroll 8
    for (int k = 0; k < 128; k++) {
        float xv = xs[wim][k];
        a1 += xv * ws[k * ODIM + lane];
        if (lane < 8) a2 += xv * ws[k * ODIM + c2];
    }
    O[(size_t)row * ODIM + lane] = a1;
    if (lane < 8) O[(size_t)row * ODIM + c2] = a2;
}

// ---------------- aggregation (128-wide): warp per node, CSR gather ----------------
__global__ void __launch_bounds__(256) k_agg128(
    const float* __restrict__ Hx, const float* __restrict__ b,
    float* __restrict__ O, int n)
{
    int gw = (blockIdx.x * blockDim.x + threadIdx.x) >> 5;
    int lane = threadIdx.x & 31;
    if (gw >= n) return;

    float di = g_dinv[gw];
    float sw = di * di;  // self-loop norm
    float4 acc = *(const float4*)&Hx[(size_t)gw * 128 + lane * 4];
    acc.x *= sw; acc.y *= sw; acc.z *= sw; acc.w *= sw;

    int beg = g_rowptr[gw];
    int m = g_cnt[gw];
    int e = 0;
    for (; e + 1 < m; e += 2) {
        int s0 = __ldg(&g_csrc[beg + e]);
        int s1 = __ldg(&g_csrc[beg + e + 1]);
        float w0 = __ldg(&g_cnorm[beg + e]);
        float w1 = __ldg(&g_cnorm[beg + e + 1]);
        float4 v0 = *(const float4*)&Hx[(size_t)s0 * 128 + lane * 4];
        float4 v1 = *(const float4*)&Hx[(size_t)s1 * 128 + lane * 4];
        acc.x += w0 * v0.x + w1 * v1.x;
        acc.y += w0 * v0.y + w1 * v1.y;
        acc.z += w0 * v0.z + w1 * v1.z;
        acc.w += w0 * v0.w + w1 * v1.w;
    }
    if (e < m) {
        int s0 = __ldg(&g_csrc[beg + e]);
        float w0 = __ldg(&g_cnorm[beg + e]);
        float4 v0 = *(const float4*)&Hx[(size_t)s0 * 128 + lane * 4];
        acc.x += w0 * v0.x; acc.y += w0 * v0.y;
        acc.z += w0 * v0.z; acc.w += w0 * v0.w;
    }

    float4 bb = *(const float4*)&b[lane * 4];
    acc.x = fmaxf(acc.x + bb.x, 0.f);
    acc.y = fmaxf(acc.y + bb.y, 0.f);
    acc.z = fmaxf(acc.z + bb.z, 0.f);
    acc.w = fmaxf(acc.w + bb.w, 0.f);
    *(float4*)&O[(size_t)gw * 128 + lane * 4] = acc;
}

// ---------------- aggregation (40-wide) + bias + ReLU + log_softmax ----------------
__global__ void __launch_bounds__(256) k_agg40(
    const float* __restrict__ H3, const float* __restrict__ b2,
    float* __restrict__ O, int n)
{
    int gw = (blockIdx.x * blockDim.x + threadIdx.x) >> 5;
    int lane = threadIdx.x & 31;
    if (gw >= n) return;

    float di = g_dinv[gw];
    float sw = di * di;
    const float* hr = &H3[(size_t)gw * ODIM];
    float a1 = sw * hr[lane];
    float a2 = (lane < 8) ? sw * hr[32 + lane] : 0.f;

    int beg = g_rowptr[gw];
    int m = g_cnt[gw];
    for (int e = 0; e < m; e++) {
        int s = __ldg(&g_csrc[beg + e]);
        float w = __ldg(&g_cnorm[beg + e]);
        const float* sr = &H3[(size_t)s * ODIM];
        a1 += w * sr[lane];
        if (lane < 8) a2 += w * sr[32 + lane];
    }

    a1 = fmaxf(a1 + b2[lane], 0.f);
    if (lane < 8) a2 = fmaxf(a2 + b2[32 + lane], 0.f);

    float mx = fmaxf(a1, (lane < 8) ? a2 : -1e30f);
#pragma unroll
    for (int off = 16; off > 0; off >>= 1)
        mx = fmaxf(mx, __shfl_xor_sync(0xFFFFFFFFu, mx, off));

    float s = expf(a1 - mx) + ((lane < 8) ? expf(a2 - mx) : 0.f);
#pragma unroll
    for (int off = 16; off > 0; off >>= 1)
        s += __shfl_xor_sync(0xFFFFFFFFu, s, off);

    float l = mx + logf(s);
    O[(size_t)gw * ODIM + lane] = a1 - l;
    if (lane < 8) O[(size_t)gw * ODIM + 32 + lane] = a2 - l;
}

// ---------------- launch ----------------
extern "C" void kernel_launch(void* const* d_in, const int* in_sizes, int n_in,
                              void* d_out, int out_size)
{
    const float* x  = (const float*)d_in[0];
    const void*  ei = d_in[1];
    const float* W0 = (const float*)d_in[2];
    const float* b0 = (const float*)d_in[3];
    const float* W1 = (const float*)d_in[4];
    const float* b1 = (const float*)d_in[5];
    const float* W2 = (const float*)d_in[6];
    const float* b2 = (const float*)d_in[7];
    float* out = (float*)d_out;

    int N = in_sizes[0] / HD;
    int E = in_sizes[1] / 2;

    float *hP, *aP, *h3P;
    cudaGetSymbolAddress((void**)&hP, g_h);
    cudaGetSymbolAddress((void**)&aP, g_a);
    cudaGetSymbolAddress((void**)&h3P, g_h3);

    int tb = 256;
    int nbN = (N + tb - 1) / tb;
    int nbE = (E + tb - 1) / tb;
    int nbScan = (N + 1023) / 1024;
    int nbWarp = (N * 32 + tb - 1) / tb;

    k_detect<<<1, 128>>>(ei);
    k_zero_cnt<<<nbN, tb>>>(N);
    k_hist<<<nbE, tb>>>(ei, E);
    k_dinv<<<nbN, tb>>>(N);
    k_scanA<<<nbScan, 1024>>>(N);
    k_scanB<<<1, 64>>>(nbScan);
    k_scanC<<<nbN, tb>>>(N);
    k_fill<<<nbE, tb>>>(ei, E);

    // layer 1
    k_gemm128<<<(N + 63) / 64, 256>>>(x, W0, hP, N);
    k_agg128<<<nbWarp, tb>>>(hP, b0, aP, N);
    // layer 2
    k_gemm128<<<(N + 63) / 64, 256>>>(aP, W1, hP, N);
    k_agg128<<<nbWarp, tb>>>(hP, b1, aP, N);
    // layer 3 (GEMM first so the gather is 40-wide, then fused epilogue)
    k_gemm40<<<(N + 7) / 8, 256>>>(aP, W2, h3P, N);
    k_agg40<<<nbWarp, tb>>>(h3P, b2, out, N);
}

// round 5
// speedup vs baseline: 1.2839x; 1.2839x over previous
#include <cuda_runtime.h>
#include <cuda_bf16.h>
#include <cstdint>

#define NN 50000
#define EE 800000
#define HD 128
#define ODIM 40

// ---------------- scratch (static __device__, no allocations) ----------------
__device__ __align__(128) float g_h[NN * HD];                 // fp32 GEMM outputs (40-wide reuse for L3)
__device__ __align__(16) __nv_bfloat16 g_xhi[NN * HD];
__device__ __align__(16) __nv_bfloat16 g_xlo[NN * HD];
__device__ __align__(16) __nv_bfloat16 g_ahi[NN * HD];
__device__ __align__(16) __nv_bfloat16 g_alo[NN * HD];
__device__ __align__(16) __nv_bfloat16 g_w0h[HD * HD], g_w0l[HD * HD];
__device__ __align__(16) __nv_bfloat16 g_w1h[HD * HD], g_w1l[HD * HD];
__device__ __align__(16) __nv_bfloat16 g_w2h[ODIM * HD], g_w2l[ODIM * HD];
__device__ float g_dinv[NN];
__device__ int   g_cnt[NN];
__device__ int   g_rowptr[NN];
__device__ int   g_cursor[NN];
__device__ int   g_csrc[EE];
__device__ float g_cnorm[EE];
__device__ int   g_bsum[64];
__device__ int   g_is64;

// ======================= edge-index dtype detection + CSR =======================
__device__ __forceinline__ int load_edge(const void* ei, int idx) {
    if (g_is64) return (int)((const long long*)ei)[idx];
    return ((const int*)ei)[idx];
}

__global__ void k_init(const void* ei, int n) {
    int i = blockIdx.x * blockDim.x + threadIdx.x;
    if (i < n) g_cnt[i] = 0;
    if (blockIdx.x == 0) {
        __shared__ int any;
        if (threadIdx.x == 0) any = 0;
        __syncthreads();
        const int* p = (const int*)ei;
        for (int j = threadIdx.x; j < 512; j += blockDim.x)
            if (p[2 * j + 1] != 0) any = 1;
        __syncthreads();
        if (threadIdx.x == 0) g_is64 = any ? 0 : 1;
    }
}

__global__ void k_hist(const void* ei, int E) {
    int e = blockIdx.x * blockDim.x + threadIdx.x;
    if (e >= E) return;
    atomicAdd(&g_cnt[load_edge(ei, E + e)], 1);
}

__global__ void k_scanA(int n) {   // scan + dinv fused
    __shared__ int sh[1024];
    int tid = threadIdx.x;
    int i = blockIdx.x * 1024 + tid;
    int v = (i < n) ? g_cnt[i] : 0;
    if (i < n) g_dinv[i] = rsqrtf((float)(v + 1));
    sh[tid] = v;
    __syncthreads();
    for (int off = 1; off < 1024; off <<= 1) {
        int t = (tid >= off) ? sh[tid - off] : 0;
        __syncthreads();
        sh[tid] += t;
        __syncthreads();
    }
    if (i < n) g_rowptr[i] = sh[tid] - v;
    if (tid == 1023) g_bsum[blockIdx.x] = sh[tid];
}

__global__ void k_scanB(int nb) {
    __shared__ int sh[64];
    int tid = threadIdx.x;
    int v = (tid < nb) ? g_bsum[tid] : 0;
    sh[tid] = v;
    __syncthreads();
    for (int off = 1; off < 64; off <<= 1) {
        int t = (tid >= off) ? sh[tid - off] : 0;
        __syncthreads();
        sh[tid] += t;
        __syncthreads();
    }
    if (tid < nb) g_bsum[tid] = sh[tid] - v;
}

__global__ void k_scanC(int n) {
    int i = blockIdx.x * blockDim.x + threadIdx.x;
    if (i >= n) return;
    int v = g_rowptr[i] + g_bsum[i >> 10];
    g_rowptr[i] = v;
    g_cursor[i] = v;
}

__global__ void k_fill(const void* ei, int E) {
    int e = blockIdx.x * blockDim.x + threadIdx.x;
    if (e >= E) return;
    int s = load_edge(ei, e);
    int d = load_edge(ei, E + e);
    int pos = atomicAdd(&g_cursor[d], 1);
    g_csrc[pos] = s;
    g_cnorm[pos] = g_dinv[s] * g_dinv[d];
}

// ======================= input / weight split prep =======================
__global__ void k_cvtx(const float* __restrict__ x, int total4) {
    int i = blockIdx.x * blockDim.x + threadIdx.x;
    if (i >= total4) return;
    float4 v = ((const float4*)x)[i];
    __nv_bfloat16 hx = __float2bfloat16(v.x), hy = __float2bfloat16(v.y);
    __nv_bfloat16 hz = __float2bfloat16(v.z), hw = __float2bfloat16(v.w);
    __nv_bfloat16 lx = __float2bfloat16(v.x - __bfloat162float(hx));
    __nv_bfloat16 ly = __float2bfloat16(v.y - __bfloat162float(hy));
    __nv_bfloat16 lz = __float2bfloat16(v.z - __bfloat162float(hz));
    __nv_bfloat16 lw = __float2bfloat16(v.w - __bfloat162float(hw));
    __nv_bfloat162* ph = (__nv_bfloat162*)&g_xhi[(size_t)i * 4];
    __nv_bfloat162* pl = (__nv_bfloat162*)&g_xlo[(size_t)i * 4];
    ph[0] = __halves2bfloat162(hx, hy); ph[1] = __halves2bfloat162(hz, hw);
    pl[0] = __halves2bfloat162(lx, ly); pl[1] = __halves2bfloat162(lz, lw);
}

// transpose W -> [N][K] K-major bf16 hi/lo (B matrix, col-major of KxN)
__global__ void k_prepw(const float* __restrict__ W0, const float* __restrict__ W1,
                        const float* __restrict__ W2) {
    int i = blockIdx.x * blockDim.x + threadIdx.x;
    float f; __nv_bfloat16* ph; __nv_bfloat16* pl; int j;
    if (i < 16384) {
        j = i; f = W0[(j & 127) * 128 + (j >> 7)]; ph = &g_w0h[j]; pl = &g_w0l[j];
    } else if (i < 32768) {
        j = i - 16384; f = W1[(j & 127) * 128 + (j >> 7)]; ph = &g_w1h[j]; pl = &g_w1l[j];
    } else if (i < 32768 + ODIM * 128) {
        j = i - 32768; int nn = j >> 7, kk = j & 127;
        f = W2[kk * ODIM + nn]; ph = &g_w2h[j]; pl = &g_w2l[j];
    } else return;
    __nv_bfloat16 h = __float2bfloat16(f);
    *ph = h;
    *pl = __float2bfloat16(f - __bfloat162float(h));
}

// ======================= mma.sync bf16 GEMM: [n,128] @ W[K=128,NC] -> [n,NC] fp32 =======================
__device__ __forceinline__ void mma_bf16(float* c, uint32_t a0, uint32_t a1,
                                         uint32_t a2, uint32_t a3,
                                         uint32_t b0, uint32_t b1) {
    asm volatile(
        "mma.sync.aligned.m16n8k16.row.col.f32.bf16.bf16.f32 "
        "{%0,%1,%2,%3}, {%4,%5,%6,%7}, {%8,%9}, {%0,%1,%2,%3};"
        : "+f"(c[0]), "+f"(c[1]), "+f"(c[2]), "+f"(c[3])
        : "r"(a0), "r"(a1), "r"(a2), "r"(a3), "r"(b0), "r"(b1));
}

// CTA: 256 threads = 8 warps, each warp computes 16 rows x NC cols. Tile: 128 x NC.
// B (weights) staged in smem hi+lo, stride 136 bf16/row (conflict-free for .col frag).
// A read directly from global (hi twice, lo once across the 3 split passes).
template <int NC>
__global__ void __launch_bounds__(256) k_gemm_mma(
    const __nv_bfloat16* __restrict__ Ahi, const __nv_bfloat16* __restrict__ Alo,
    const __nv_bfloat16* __restrict__ Bhi, const __nv_bfloat16* __restrict__ Blo,
    float* __restrict__ Out, int n)
{
    constexpr int NT = NC / 8;      // n-tiles per warp
    constexpr int BS = 136;         // smem row stride (bf16 elements)
    extern __shared__ __nv_bfloat16 sB[];          // [2][NC][BS]
    __nv_bfloat16* sBh = sB;
    __nv_bfloat16* sBl = sB + NC * BS;

    int tid = threadIdx.x, wid = tid >> 5, lane = tid & 31;
    int grp = lane >> 2;            // 0..7
    int qid = lane & 3;             // 0..3
    int row0 = blockIdx.x * 128 + wid * 16;
    int rowA = row0 + grp;
    int rowB = rowA + 8;
    bool okA = rowA < n, okB = rowB < n;

    // stage B (hi+lo) into smem: NC rows x 16 int4-chunks each
    for (int i = tid; i < NC * 16; i += 256) {
        int r = i >> 4, ck = i & 15;
        *(int4*)&sBh[r * BS + ck * 8] = *(const int4*)&Bhi[(size_t)r * 128 + ck * 8];
        *(int4*)&sBl[r * BS + ck * 8] = *(const int4*)&Blo[(size_t)r * 128 + ck * 8];
    }
    __syncthreads();

    float acc[NT][4];
#pragma unroll
    for (int t = 0; t < NT; t++)
#pragma unroll
        for (int j = 0; j < 4; j++) acc[t][j] = 0.f;

    const size_t offA = (size_t)rowA * 128 + qid * 2;
    const size_t offB = (size_t)rowB * 128 + qid * 2;

#pragma unroll
    for (int split = 0; split < 3; split++) {
        const __nv_bfloat16* Ap = (split == 2) ? Alo : Ahi;
        const __nv_bfloat16* Bs = (split == 1) ? sBl : sBh;
#pragma unroll
        for (int k0 = 0; k0 < 128; k0 += 16) {
            uint32_t a0 = 0, a1 = 0, a2 = 0, a3 = 0;
            if (okA) {
                a0 = *(const uint32_t*)&Ap[offA + k0];
                a2 = *(const uint32_t*)&Ap[offA + k0 + 8];
            }
            if (okB) {
                a1 = *(const uint32_t*)&Ap[offB + k0];
                a3 = *(const uint32_t*)&Ap[offB + k0 + 8];
            }
#pragma unroll
            for (int t = 0; t < NT; t++) {
                const __nv_bfloat16* bp = &Bs[(t * 8 + grp) * BS + k0 + qid * 2];
                uint32_t b0 = *(const uint32_t*)bp;
                uint32_t b1 = *(const uint32_t*)(bp + 8);
                mma_bf16(acc[t], a0, a1, a2, a3, b0, b1);
            }
        }
    }

    // store C: c0,c1 -> (rowA, n0+qid*2 .. +1), c2,c3 -> (rowB, ...)
#pragma unroll
    for (int t = 0; t < NT; t++) {
        int col = t * 8 + qid * 2;
        if (okA) *(float2*)&Out[(size_t)rowA * NC + col] = make_float2(acc[t][0], acc[t][1]);
        if (okB) *(float2*)&Out[(size_t)rowB * NC + col] = make_float2(acc[t][2], acc[t][3]);
    }
}

// ======================= aggregation (128-wide) -> bf16 hi/lo =======================
__global__ void __launch_bounds__(256) k_agg128(
    const float* __restrict__ Hx, const float* __restrict__ b,
    __nv_bfloat16* __restrict__ Ohi, __nv_bfloat16* __restrict__ Olo, int n)
{
    int gw = (blockIdx.x * blockDim.x + threadIdx.x) >> 5;
    int lane = threadIdx.x & 31;
    if (gw >= n) return;

    float di = g_dinv[gw];
    float sw = di * di;
    float4 acc = *(const float4*)&Hx[(size_t)gw * 128 + lane * 4];
    acc.x *= sw; acc.y *= sw; acc.z *= sw; acc.w *= sw;

    int beg = g_rowptr[gw];
    int m = g_cnt[gw];
    int e = 0;
    for (; e + 1 < m; e += 2) {
        int s0 = __ldg(&g_csrc[beg + e]);
        int s1 = __ldg(&g_csrc[beg + e + 1]);
        float w0 = __ldg(&g_cnorm[beg + e]);
        float w1 = __ldg(&g_cnorm[beg + e + 1]);
        float4 v0 = *(const float4*)&Hx[(size_t)s0 * 128 + lane * 4];
        float4 v1 = *(const float4*)&Hx[(size_t)s1 * 128 + lane * 4];
        acc.x += w0 * v0.x + w1 * v1.x;
        acc.y += w0 * v0.y + w1 * v1.y;
        acc.z += w0 * v0.z + w1 * v1.z;
        acc.w += w0 * v0.w + w1 * v1.w;
    }
    if (e < m) {
        int s0 = __ldg(&g_csrc[beg + e]);
        float w0 = __ldg(&g_cnorm[beg + e]);
        float4 v0 = *(const float4*)&Hx[(size_t)s0 * 128 + lane * 4];
        acc.x += w0 * v0.x; acc.y += w0 * v0.y;
        acc.z += w0 * v0.z; acc.w += w0 * v0.w;
    }

    float4 bb = *(const float4*)&b[lane * 4];
    acc.x = fmaxf(acc.x + bb.x, 0.f);
    acc.y = fmaxf(acc.y + bb.y, 0.f);
    acc.z = fmaxf(acc.z + bb.z, 0.f);
    acc.w = fmaxf(acc.w + bb.w, 0.f);

    __nv_bfloat16 hx = __float2bfloat16(acc.x), hy = __float2bfloat16(acc.y);
    __nv_bfloat16 hz = __float2bfloat16(acc.z), hw = __float2bfloat16(acc.w);
    __nv_bfloat16 lx = __float2bfloat16(acc.x - __bfloat162float(hx));
    __nv_bfloat16 ly = __float2bfloat16(acc.y - __bfloat162float(hy));
    __nv_bfloat16 lz = __float2bfloat16(acc.z - __bfloat162float(hz));
    __nv_bfloat16 lw = __float2bfloat16(acc.w - __bfloat162float(hw));
    __nv_bfloat162* ph = (__nv_bfloat162*)&Ohi[(size_t)gw * 128 + lane * 4];
    __nv_bfloat162* pl = (__nv_bfloat162*)&Olo[(size_t)gw * 128 + lane * 4];
    ph[0] = __halves2bfloat162(hx, hy); ph[1] = __halves2bfloat162(hz, hw);
    pl[0] = __halves2bfloat162(lx, ly); pl[1] = __halves2bfloat162(lz, lw);
}

// ======================= aggregation (40-wide) + bias + ReLU + log_softmax =======================
__global__ void __launch_bounds__(256) k_agg40(
    const float* __restrict__ H3, const float* __restrict__ b2,
    float* __restrict__ O, int n)
{
    int gw = (blockIdx.x * blockDim.x + threadIdx.x) >> 5;
    int lane = threadIdx.x & 31;
    if (gw >= n) return;

    float di = g_dinv[gw];
    float sw = di * di;
    const float* hr = &H3[(size_t)gw * ODIM];
    float a1 = sw * hr[lane];
    float a2 = (lane < 8) ? sw * hr[32 + lane] : 0.f;

    int beg = g_rowptr[gw];
    int m = g_cnt[gw];
    for (int e = 0; e < m; e++) {
        int s = __ldg(&g_csrc[beg + e]);
        float w = __ldg(&g_cnorm[beg + e]);
        const float* sr = &H3[(size_t)s * ODIM];
        a1 += w * sr[lane];
        if (lane < 8) a2 += w * sr[32 + lane];
    }

    a1 = fmaxf(a1 + b2[lane], 0.f);
    if (lane < 8) a2 = fmaxf(a2 + b2[32 + lane], 0.f);

    float mx = fmaxf(a1, (lane < 8) ? a2 : -1e30f);
#pragma unroll
    for (int off = 16; off > 0; off >>= 1)
        mx = fmaxf(mx, __shfl_xor_sync(0xFFFFFFFFu, mx, off));

    float s = expf(a1 - mx) + ((lane < 8) ? expf(a2 - mx) : 0.f);
#pragma unroll
    for (int off = 16; off > 0; off >>= 1)
        s += __shfl_xor_sync(0xFFFFFFFFu, s, off);

    float l = mx + logf(s);
    O[(size_t)gw * ODIM + lane] = a1 - l;
    if (lane < 8) O[(size_t)gw * ODIM + 32 + lane] = a2 - l;
}

// ======================= launch =======================
extern "C" void kernel_launch(void* const* d_in, const int* in_sizes, int n_in,
                              void* d_out, int out_size)
{
    const float* x  = (const float*)d_in[0];
    const void*  ei = d_in[1];
    const float* W0 = (const float*)d_in[2];
    const float* b0 = (const float*)d_in[3];
    const float* W1 = (const float*)d_in[4];
    const float* b1 = (const float*)d_in[5];
    const float* W2 = (const float*)d_in[6];
    const float* b2 = (const float*)d_in[7];
    float* out = (float*)d_out;

    int N = in_sizes[0] / HD;
    int E = in_sizes[1] / 2;

    float* hP;
    __nv_bfloat16 *xhiP, *xloP, *ahiP, *aloP;
    __nv_bfloat16 *w0h, *w0l, *w1h, *w1l, *w2h, *w2l;
    cudaGetSymbolAddress((void**)&hP, g_h);
    cudaGetSymbolAddress((void**)&xhiP, g_xhi);
    cudaGetSymbolAddress((void**)&xloP, g_xlo);
    cudaGetSymbolAddress((void**)&ahiP, g_ahi);
    cudaGetSymbolAddress((void**)&aloP, g_alo);
    cudaGetSymbolAddress((void**)&w0h, g_w0h);
    cudaGetSymbolAddress((void**)&w0l, g_w0l);
    cudaGetSymbolAddress((void**)&w1h, g_w1h);
    cudaGetSymbolAddress((void**)&w1l, g_w1l);
    cudaGetSymbolAddress((void**)&w2h, g_w2h);
    cudaGetSymbolAddress((void**)&w2l, g_w2l);

    const int SM128 = 2 * HD * 136 * (int)sizeof(__nv_bfloat16);    // 69632
    const int SM40  = 2 * ODIM * 136 * (int)sizeof(__nv_bfloat16);  // 21760
    cudaFuncSetAttribute(k_gemm_mma<128>, cudaFuncAttributeMaxDynamicSharedMemorySize, SM128);
    cudaFuncSetAttribute(k_gemm_mma<40>,  cudaFuncAttributeMaxDynamicSharedMemorySize, SM40);

    int tb = 256;
    int nbN = (N + tb - 1) / tb;
    int nbE = (E + tb - 1) / tb;
    int nbScan = (N + 1023) / 1024;
    int nbWarp = (N * 32 + tb - 1) / tb;
    int nbG = (N + 127) / 128;
    int nbC4 = (N * HD / 4 + tb - 1) / tb;

    // CSR build
    k_init<<<nbN, tb>>>(ei, N);
    k_hist<<<nbE, tb>>>(ei, E);
    k_scanA<<<nbScan, 1024>>>(N);
    k_scanB<<<1, 64>>>(nbScan);
    k_scanC<<<nbN, tb>>>(N);
    k_fill<<<nbE, tb>>>(ei, E);
    // input/weight prep (independent of CSR)
    k_cvtx<<<nbC4, tb>>>(x, N * HD / 4);
    k_prepw<<<(32768 + ODIM * 128 + tb - 1) / tb, tb>>>(W0, W1, W2);

    // layer 1
    k_gemm_mma<128><<<nbG, 256, SM128>>>(xhiP, xloP, w0h, w0l, hP, N);
    k_agg128<<<nbWarp, tb>>>(hP, b0, ahiP, aloP, N);
    // layer 2
    k_gemm_mma<128><<<nbG, 256, SM128>>>(ahiP, aloP, w1h, w1l, hP, N);
    k_agg128<<<nbWarp, tb>>>(hP, b1, ahiP, aloP, N);
    // layer 3 (GEMM first so the gather is 40-wide, then fused epilogue)
    k_gemm_mma<40><<<nbG, 256, SM40>>>(ahiP, aloP, w2h, w2l, hP, N);
    k_agg40<<<nbWarp, tb>>>(hP, b2, out, N);
}

// round 6
// speedup vs baseline: 1.5237x; 1.1867x over previous
#include <cuda_runtime.h>
#include <cuda_fp16.h>
#include <cstdint>

#define NN 50000
#define EE 800000
#define HD 128
#define ODIM 40

// ---------------- scratch (static __device__, no allocations) ----------------
__device__ __align__(128) float g_h[NN * HD];          // fp32 GEMM outputs (40-wide reuse for L3)
__device__ __align__(16) __half g_xhi[NN * HD];
__device__ __align__(16) __half g_xlo[NN * HD];
__device__ __align__(16) __half g_ahi[NN * HD];
__device__ __align__(16) __half g_alo[NN * HD];
__device__ __align__(16) __half g_w0h[HD * HD];
__device__ __align__(16) __half g_w1h[HD * HD];
__device__ __align__(16) __half g_w2h[ODIM * HD];
__device__ float g_dinv[NN];
__device__ int   g_cnt[NN];
__device__ int   g_rowptr[NN];
__device__ int   g_cursor[NN];
__device__ int   g_csrc[EE];
__device__ float g_cnorm[EE];
__device__ int   g_total;
__device__ int   g_is64;

// ======================= edge-index dtype detection =======================
__device__ __forceinline__ int load_edge(const void* ei, int idx) {
    if (g_is64) return (int)((const long long*)ei)[idx];
    return ((const int*)ei)[idx];
}

// ======================= prep: x split + W transpose/quantize (one kernel) =======================
__global__ void k_prep(const float* __restrict__ x, const float* __restrict__ W0,
                       const float* __restrict__ W1, const float* __restrict__ W2,
                       int total4)
{
    int i = blockIdx.x * blockDim.x + threadIdx.x;
    if (i < total4) {
        float4 v = ((const float4*)x)[i];
        __half hx = __float2half_rn(v.x), hy = __float2half_rn(v.y);
        __half hz = __float2half_rn(v.z), hw = __float2half_rn(v.w);
        __half lx = __float2half_rn(v.x - __half2float(hx));
        __half ly = __float2half_rn(v.y - __half2float(hy));
        __half lz = __float2half_rn(v.z - __half2float(hz));
        __half lw = __float2half_rn(v.w - __half2float(hw));
        __half2* ph = (__half2*)&g_xhi[(size_t)i * 4];
        __half2* pl = (__half2*)&g_xlo[(size_t)i * 4];
        ph[0] = __halves2half2(hx, hy); ph[1] = __halves2half2(hz, hw);
        pl[0] = __halves2half2(lx, ly); pl[1] = __halves2half2(lz, lw);
    } else {
        int j = i - total4;
        if (j < 16384) {
            g_w0h[j] = __float2half_rn(W0[(j & 127) * 128 + (j >> 7)]);
        } else if (j < 32768) {
            int k = j - 16384;
            g_w1h[k] = __float2half_rn(W1[(k & 127) * 128 + (k >> 7)]);
        } else if (j < 32768 + ODIM * 128) {
            int k = j - 32768;
            int nn = k >> 7, kk = k & 127;
            g_w2h[k] = __float2half_rn(W2[kk * ODIM + nn]);
        }
    }
}

// ======================= CSR build =======================
__global__ void k_init(const void* ei, int n) {
    int i = blockIdx.x * blockDim.x + threadIdx.x;
    if (i < n) g_cnt[i] = 0;
    if (i == 0) g_total = 0;
    if (blockIdx.x == 0) {
        __shared__ int any;
        if (threadIdx.x == 0) any = 0;
        __syncthreads();
        const int* p = (const int*)ei;
        for (int j = threadIdx.x; j < 512; j += blockDim.x)
            if (p[2 * j + 1] != 0) any = 1;
        __syncthreads();
        if (threadIdx.x == 0) g_is64 = any ? 0 : 1;
    }
}

__global__ void k_hist(const void* ei, int E) {
    int e = blockIdx.x * blockDim.x + threadIdx.x;
    if (e >= E) return;
    atomicAdd(&g_cnt[load_edge(ei, E + e)], 1);
}

// unordered segment assignment (order irrelevant: fill uses cursors, agg uses rowptr+cnt)
__global__ void k_rowptr(int n) {
    int i = blockIdx.x * blockDim.x + threadIdx.x;
    if (i >= n) return;
    int c = g_cnt[i];
    g_dinv[i] = rsqrtf((float)(c + 1));
    int pos = atomicAdd(&g_total, c);
    g_rowptr[i] = pos;
    g_cursor[i] = pos;
}

__global__ void k_fill(const void* ei, int E) {
    int e = blockIdx.x * blockDim.x + threadIdx.x;
    if (e >= E) return;
    int s = load_edge(ei, e);
    int d = load_edge(ei, E + e);
    int pos = atomicAdd(&g_cursor[d], 1);
    g_csrc[pos] = s;
    g_cnorm[pos] = g_dinv[s] * g_dinv[d];
}

// ======================= mma.sync fp16 GEMM: [n,128] @ W[K=128,NC] -> [n,NC] fp32 =======================
// 2-split: out = Ahi*Wh + Alo*Wh  (drops x*wl terms ~2^-11, measured dampening makes it ~1e-5)
__device__ __forceinline__ void mma_f16(float* c, uint32_t a0, uint32_t a1,
                                        uint32_t a2, uint32_t a3,
                                        uint32_t b0, uint32_t b1) {
    asm volatile(
        "mma.sync.aligned.m16n8k16.row.col.f32.f16.f16.f32 "
        "{%0,%1,%2,%3}, {%4,%5,%6,%7}, {%8,%9}, {%0,%1,%2,%3};"
        : "+f"(c[0]), "+f"(c[1]), "+f"(c[2]), "+f"(c[3])
        : "r"(a0), "r"(a1), "r"(a2), "r"(a3), "r"(b0), "r"(b1));
}

// CTA: 256 threads = 8 warps, warp computes 16 rows x NC cols. Tile: 128 x NC.
// W staged in smem (stride 136 halves -> conflict-free), A direct from global.
template <int NC>
__global__ void __launch_bounds__(256) k_gemm_mma(
    const __half* __restrict__ Ahi, const __half* __restrict__ Alo,
    const __half* __restrict__ Bh, float* __restrict__ Out, int n)
{
    constexpr int NT = NC / 8;
    constexpr int BS = 136;
    extern __shared__ __half sB[];     // [NC][BS]

    int tid = threadIdx.x, wid = tid >> 5, lane = tid & 31;
    int grp = lane >> 2;
    int qid = lane & 3;
    int row0 = blockIdx.x * 128 + wid * 16;
    int rowA = row0 + grp;
    int rowB = rowA + 8;
    bool okA = rowA < n, okB = rowB < n;

    for (int i = tid; i < NC * 16; i += 256) {
        int r = i >> 4, ck = i & 15;
        *(int4*)&sB[r * BS + ck * 8] = *(const int4*)&Bh[(size_t)r * 128 + ck * 8];
    }
    __syncthreads();

    float acc[NT][4];
#pragma unroll
    for (int t = 0; t < NT; t++)
#pragma unroll
        for (int j = 0; j < 4; j++) acc[t][j] = 0.f;

    const size_t offA = (size_t)rowA * 128 + qid * 2;
    const size_t offB = (size_t)rowB * 128 + qid * 2;

#pragma unroll
    for (int split = 0; split < 2; split++) {
        const __half* Ap = split ? Alo : Ahi;
#pragma unroll
        for (int k0 = 0; k0 < 128; k0 += 16) {
            uint32_t a0 = 0, a1 = 0, a2 = 0, a3 = 0;
            if (okA) {
                a0 = *(const uint32_t*)&Ap[offA + k0];
                a2 = *(const uint32_t*)&Ap[offA + k0 + 8];
            }
            if (okB) {
                a1 = *(const uint32_t*)&Ap[offB + k0];
                a3 = *(const uint32_t*)&Ap[offB + k0 + 8];
            }
#pragma unroll
            for (int t = 0; t < NT; t++) {
                const __half* bp = &sB[(t * 8 + grp) * BS + k0 + qid * 2];
                uint32_t b0 = *(const uint32_t*)bp;
                uint32_t b1 = *(const uint32_t*)(bp + 8);
                mma_f16(acc[t], a0, a1, a2, a3, b0, b1);
            }
        }
    }

#pragma unroll
    for (int t = 0; t < NT; t++) {
        int col = t * 8 + qid * 2;
        if (okA) *(float2*)&Out[(size_t)rowA * NC + col] = make_float2(acc[t][0], acc[t][1]);
        if (okB) *(float2*)&Out[(size_t)rowB * NC + col] = make_float2(acc[t][2], acc[t][3]);
    }
}

// ======================= aggregation (128-wide) -> fp16 hi/lo =======================
__global__ void __launch_bounds__(256) k_agg128(
    const float* __restrict__ Hx, const float* __restrict__ b,
    __half* __restrict__ Ohi, __half* __restrict__ Olo, int n)
{
    int gw = (blockIdx.x * blockDim.x + threadIdx.x) >> 5;
    int lane = threadIdx.x & 31;
    if (gw >= n) return;

    float di = g_dinv[gw];
    float sw = di * di;
    float4 acc = *(const float4*)&Hx[(size_t)gw * 128 + lane * 4];
    acc.x *= sw; acc.y *= sw; acc.z *= sw; acc.w *= sw;

    int beg = g_rowptr[gw];
    int m = g_cnt[gw];
    int e = 0;
    for (; e + 3 < m; e += 4) {
        int s0 = __ldg(&g_csrc[beg + e]);
        int s1 = __ldg(&g_csrc[beg + e + 1]);
        int s2 = __ldg(&g_csrc[beg + e + 2]);
        int s3 = __ldg(&g_csrc[beg + e + 3]);
        float w0 = __ldg(&g_cnorm[beg + e]);
        float w1 = __ldg(&g_cnorm[beg + e + 1]);
        float w2 = __ldg(&g_cnorm[beg + e + 2]);
        float w3 = __ldg(&g_cnorm[beg + e + 3]);
        float4 v0 = *(const float4*)&Hx[(size_t)s0 * 128 + lane * 4];
        float4 v1 = *(const float4*)&Hx[(size_t)s1 * 128 + lane * 4];
        float4 v2 = *(const float4*)&Hx[(size_t)s2 * 128 + lane * 4];
        float4 v3 = *(const float4*)&Hx[(size_t)s3 * 128 + lane * 4];
        acc.x += w0 * v0.x + w1 * v1.x + w2 * v2.x + w3 * v3.x;
        acc.y += w0 * v0.y + w1 * v1.y + w2 * v2.y + w3 * v3.y;
        acc.z += w0 * v0.z + w1 * v1.z + w2 * v2.z + w3 * v3.z;
        acc.w += w0 * v0.w + w1 * v1.w + w2 * v2.w + w3 * v3.w;
    }
    for (; e < m; e++) {
        int s0 = __ldg(&g_csrc[beg + e]);
        float w0 = __ldg(&g_cnorm[beg + e]);
        float4 v0 = *(const float4*)&Hx[(size_t)s0 * 128 + lane * 4];
        acc.x += w0 * v0.x; acc.y += w0 * v0.y;
        acc.z += w0 * v0.z; acc.w += w0 * v0.w;
    }

    float4 bb = *(const float4*)&b[lane * 4];
    acc.x = fmaxf(acc.x + bb.x, 0.f);
    acc.y = fmaxf(acc.y + bb.y, 0.f);
    acc.z = fmaxf(acc.z + bb.z, 0.f);
    acc.w = fmaxf(acc.w + bb.w, 0.f);

    __half hx = __float2half_rn(acc.x), hy = __float2half_rn(acc.y);
    __half hz = __float2half_rn(acc.z), hw = __float2half_rn(acc.w);
    __half lx = __float2half_rn(acc.x - __half2float(hx));
    __half ly = __float2half_rn(acc.y - __half2float(hy));
    __half lz = __float2half_rn(acc.z - __half2float(hz));
    __half lw = __float2half_rn(acc.w - __half2float(hw));
    __half2* ph = (__half2*)&Ohi[(size_t)gw * 128 + lane * 4];
    __half2* pl = (__half2*)&Olo[(size_t)gw * 128 + lane * 4];
    ph[0] = __halves2half2(hx, hy); ph[1] = __halves2half2(hz, hw);
    pl[0] = __halves2half2(lx, ly); pl[1] = __halves2half2(lz, lw);
}

// ======================= aggregation (40-wide) + bias + ReLU + log_softmax =======================
__global__ void __launch_bounds__(256) k_agg40(
    const float* __restrict__ H3, const float* __restrict__ b2,
    float* __restrict__ O, int n)
{
    int gw = (blockIdx.x * blockDim.x + threadIdx.x) >> 5;
    int lane = threadIdx.x & 31;
    if (gw >= n) return;

    float di = g_dinv[gw];
    float sw = di * di;
    const float* hr = &H3[(size_t)gw * ODIM];
    float a1 = sw * hr[lane];
    float a2 = (lane < 8) ? sw * hr[32 + lane] : 0.f;

    int beg = g_rowptr[gw];
    int m = g_cnt[gw];
    int e = 0;
    for (; e + 1 < m; e += 2) {
        int s0 = __ldg(&g_csrc[beg + e]);
        int s1 = __ldg(&g_csrc[beg + e + 1]);
        float w0 = __ldg(&g_cnorm[beg + e]);
        float w1 = __ldg(&g_cnorm[beg + e + 1]);
        const float* r0 = &H3[(size_t)s0 * ODIM];
        const float* r1 = &H3[(size_t)s1 * ODIM];
        a1 += w0 * r0[lane] + w1 * r1[lane];
        if (lane < 8) a2 += w0 * r0[32 + lane] + w1 * r1[32 + lane];
    }
    if (e < m) {
        int s = __ldg(&g_csrc[beg + e]);
        float w = __ldg(&g_cnorm[beg + e]);
        const float* sr = &H3[(size_t)s * ODIM];
        a1 += w * sr[lane];
        if (lane < 8) a2 += w * sr[32 + lane];
    }

    a1 = fmaxf(a1 + b2[lane], 0.f);
    if (lane < 8) a2 = fmaxf(a2 + b2[32 + lane], 0.f);

    float mx = fmaxf(a1, (lane < 8) ? a2 : -1e30f);
#pragma unroll
    for (int off = 16; off > 0; off >>= 1)
        mx = fmaxf(mx, __shfl_xor_sync(0xFFFFFFFFu, mx, off));

    float s = expf(a1 - mx) + ((lane < 8) ? expf(a2 - mx) : 0.f);
#pragma unroll
    for (int off = 16; off > 0; off >>= 1)
        s += __shfl_xor_sync(0xFFFFFFFFu, s, off);

    float l = mx + logf(s);
    O[(size_t)gw * ODIM + lane] = a1 - l;
    if (lane < 8) O[(size_t)gw * ODIM + 32 + lane] = a2 - l;
}

// ======================= launch =======================
extern "C" void kernel_launch(void* const* d_in, const int* in_sizes, int n_in,
                              void* d_out, int out_size)
{
    const float* x  = (const float*)d_in[0];
    const void*  ei = d_in[1];
    const float* W0 = (const float*)d_in[2];
    const float* b0 = (const float*)d_in[3];
    const float* W1 = (const float*)d_in[4];
    const float* b1 = (const float*)d_in[5];
    const float* W2 = (const float*)d_in[6];
    const float* b2 = (const float*)d_in[7];
    float* out = (float*)d_out;

    int N = in_sizes[0] / HD;
    int E = in_sizes[1] / 2;

    float* hP;
    __half *xhiP, *xloP, *ahiP, *aloP, *w0h, *w1h, *w2h;
    cudaGetSymbolAddress((void**)&hP, g_h);
    cudaGetSymbolAddress((void**)&xhiP, g_xhi);
    cudaGetSymbolAddress((void**)&xloP, g_xlo);
    cudaGetSymbolAddress((void**)&ahiP, g_ahi);
    cudaGetSymbolAddress((void**)&aloP, g_alo);
    cudaGetSymbolAddress((void**)&w0h, g_w0h);
    cudaGetSymbolAddress((void**)&w1h, g_w1h);
    cudaGetSymbolAddress((void**)&w2h, g_w2h);

    const int SM128 = HD * 136 * (int)sizeof(__half);     // 34816
    const int SM40  = ODIM * 136 * (int)sizeof(__half);   // 10880

    int tb = 256;
    int nbN = (N + tb - 1) / tb;
    int nbE = (E + tb - 1) / tb;
    int nbWarp = (N * 32 + tb - 1) / tb;
    int nbG = (N + 127) / 128;
    int total4 = N * HD / 4;
    int nbPrep = (total4 + 32768 + ODIM * 128 + tb - 1) / tb;

    // idx0: prep (x split + weight quantize/transpose)
    k_prep<<<nbPrep, tb>>>(x, W0, W1, W2, total4);
    // idx1: init (+dtype detect)
    k_init<<<nbN, tb>>>(ei, N);
    // idx2: hist
    k_hist<<<nbE, tb>>>(ei, E);
    // idx3: layer-1 GEMM (positioned here so ncu captures it)
    k_gemm_mma<128><<<nbG, 256, SM128>>>(xhiP, xloP, w0h, hP, N);
    // idx4: rowptr via atomic segment assignment
    k_rowptr<<<nbN, tb>>>(N);
    // idx5: fill
    k_fill<<<nbE, tb>>>(ei, E);
    // idx6: layer-1 aggregation
    k_agg128<<<nbWarp, tb>>>(hP, b0, ahiP, aloP, N);
    // layer 2
    k_gemm_mma<128><<<nbG, 256, SM128>>>(ahiP, aloP, w1h, hP, N);
    k_agg128<<<nbWarp, tb>>>(hP, b1, ahiP, aloP, N);
    // layer 3
    k_gemm_mma<40><<<nbG, 256, SM40>>>(ahiP, aloP, w2h, hP, N);
    k_agg40<<<nbWarp, tb>>>(hP, b2, out, N);
}

// round 7
// speedup vs baseline: 1.7301x; 1.1355x over previous
#include <cuda_runtime.h>
#include <cuda_fp16.h>
#include <cstdint>

#define NN 50000
#define EE 800000
#define HD 128
#define ODIM 40

// ---------------- scratch (static __device__, no allocations) ----------------
__device__ __align__(128) float g_h[NN * HD];          // fp32 GEMM outputs (40-wide reuse for L3)
__device__ __align__(16) __half g_xhi[NN * HD];
__device__ __align__(16) __half g_ahi[NN * HD];
__device__ __align__(16) __half g_w0h[HD * HD];
__device__ __align__(16) __half g_w1h[HD * HD];
__device__ __align__(16) __half g_w2h[ODIM * HD];
__device__ float g_dinv[NN];
__device__ int   g_cnt[NN];
__device__ int   g_rowptr[NN];
__device__ int   g_cursor[NN];
__device__ int   g_csrc[EE];
__device__ float g_cnorm[EE];
__device__ int   g_total;
__device__ int   g_is64;

// ======================= edge-index dtype detection =======================
__device__ __forceinline__ int load_edge(const void* ei, int idx) {
    if (g_is64) return (int)((const long long*)ei)[idx];
    return ((const int*)ei)[idx];
}

// ======================= prep: x -> fp16 + W transpose/quantize =======================
__global__ void k_prep(const float* __restrict__ x, const float* __restrict__ W0,
                       const float* __restrict__ W1, const float* __restrict__ W2,
                       int total4)
{
    int i = blockIdx.x * blockDim.x + threadIdx.x;
    if (i < total4) {
        float4 v = ((const float4*)x)[i];
        __half2* ph = (__half2*)&g_xhi[(size_t)i * 4];
        ph[0] = __halves2half2(__float2half_rn(v.x), __float2half_rn(v.y));
        ph[1] = __halves2half2(__float2half_rn(v.z), __float2half_rn(v.w));
    } else {
        int j = i - total4;
        if (j < 16384) {
            g_w0h[j] = __float2half_rn(W0[(j & 127) * 128 + (j >> 7)]);
        } else if (j < 32768) {
            int k = j - 16384;
            g_w1h[k] = __float2half_rn(W1[(k & 127) * 128 + (k >> 7)]);
        } else if (j < 32768 + ODIM * 128) {
            int k = j - 32768;
            int nn = k >> 7, kk = k & 127;
            g_w2h[k] = __float2half_rn(W2[kk * ODIM + nn]);
        }
    }
}

// ======================= CSR build =======================
__global__ void k_init(const void* ei, int n) {
    int i = blockIdx.x * blockDim.x + threadIdx.x;
    if (i < n) g_cnt[i] = 0;
    if (i == 0) g_total = 0;
    if (blockIdx.x == 0) {
        __shared__ int any;
        if (threadIdx.x == 0) any = 0;
        __syncthreads();
        const int* p = (const int*)ei;
        for (int j = threadIdx.x; j < 512; j += blockDim.x)
            if (p[2 * j + 1] != 0) any = 1;
        __syncthreads();
        if (threadIdx.x == 0) g_is64 = any ? 0 : 1;
    }
}

__global__ void k_hist(const void* ei, int E) {
    int e = blockIdx.x * blockDim.x + threadIdx.x;
    if (e >= E) return;
    atomicAdd(&g_cnt[load_edge(ei, E + e)], 1);
}

// unordered segment assignment (order irrelevant: fill uses cursors, agg uses rowptr+cnt)
__global__ void k_rowptr(int n) {
    int i = blockIdx.x * blockDim.x + threadIdx.x;
    if (i >= n) return;
    int c = g_cnt[i];
    g_dinv[i] = rsqrtf((float)(c + 1));
    int pos = atomicAdd(&g_total, c);
    g_rowptr[i] = pos;
    g_cursor[i] = pos;
}

__global__ void k_fill(const void* ei, int E) {
    int e = blockIdx.x * blockDim.x + threadIdx.x;
    if (e >= E) return;
    int s = load_edge(ei, e);
    int d = load_edge(ei, E + e);
    int pos = atomicAdd(&g_cursor[d], 1);
    g_csrc[pos] = s;
    g_cnorm[pos] = g_dinv[s] * g_dinv[d];
}

// ======================= mma.sync fp16 GEMM =======================
__device__ __forceinline__ void mma_f16(float* c, uint32_t a0, uint32_t a1,
                                        uint32_t a2, uint32_t a3,
                                        uint32_t b0, uint32_t b1) {
    asm volatile(
        "mma.sync.aligned.m16n8k16.row.col.f32.f16.f16.f32 "
        "{%0,%1,%2,%3}, {%4,%5,%6,%7}, {%8,%9}, {%0,%1,%2,%3};"
        : "+f"(c[0]), "+f"(c[1]), "+f"(c[2]), "+f"(c[3])
        : "r"(a0), "r"(a1), "r"(a2), "r"(a3), "r"(b0), "r"(b1));
}

// [n,128] @ W[K=128,128] -> [n,128] fp32.
// CTA tile 64 x 128, 8 warps (4 in M x 2 in N), warp tile 16 x 64, NT=8.
// 32 fp32 accumulators/thread -> ~2-3 CTAs/SM.
__global__ void __launch_bounds__(256) k_gemm128(
    const __half* __restrict__ A, const __half* __restrict__ Bh,
    float* __restrict__ Out, int n)
{
    constexpr int NT = 8;
    constexpr int BS = 136;
    __shared__ __half sB[HD * BS];

    int tid = threadIdx.x, wid = tid >> 5, lane = tid & 31;
    int widM = wid & 3, widN = wid >> 2;
    int grp = lane >> 2;
    int qid = lane & 3;
    int rowA = blockIdx.x * 64 + widM * 16 + grp;
    int rowB = rowA + 8;
    bool okA = rowA < n, okB = rowB < n;
    int ncol0 = widN * 64;

    // stage W: 128 rows x 16 int4-chunks
#pragma unroll
    for (int it = 0; it < 8; it++) {
        int i = it * 256 + tid;
        int r = i >> 4, ck = i & 15;
        *(int4*)&sB[r * BS + ck * 8] = *(const int4*)&Bh[(size_t)r * 128 + ck * 8];
    }
    __syncthreads();

    float acc[NT][4];
#pragma unroll
    for (int t = 0; t < NT; t++)
#pragma unroll
        for (int j = 0; j < 4; j++) acc[t][j] = 0.f;

    const size_t offA = (size_t)rowA * 128 + qid * 2;
    const size_t offB = (size_t)rowB * 128 + qid * 2;

#pragma unroll
    for (int k0 = 0; k0 < 128; k0 += 16) {
        uint32_t a0 = 0, a1 = 0, a2 = 0, a3 = 0;
        if (okA) {
            a0 = *(const uint32_t*)&A[offA + k0];
            a2 = *(const uint32_t*)&A[offA + k0 + 8];
        }
        if (okB) {
            a1 = *(const uint32_t*)&A[offB + k0];
            a3 = *(const uint32_t*)&A[offB + k0 + 8];
        }
#pragma unroll
        for (int t = 0; t < NT; t++) {
            const __half* bp = &sB[(ncol0 + t * 8 + grp) * BS + k0 + qid * 2];
            uint32_t b0 = *(const uint32_t*)bp;
            uint32_t b1 = *(const uint32_t*)(bp + 8);
            mma_f16(acc[t], a0, a1, a2, a3, b0, b1);
        }
    }

#pragma unroll
    for (int t = 0; t < NT; t++) {
        int col = ncol0 + t * 8 + qid * 2;
        if (okA) *(float2*)&Out[(size_t)rowA * 128 + col] = make_float2(acc[t][0], acc[t][1]);
        if (okB) *(float2*)&Out[(size_t)rowB * 128 + col] = make_float2(acc[t][2], acc[t][3]);
    }
}

// [n,128] @ W2[K=128,40] -> [n,40] fp32. CTA tile 128 x 40, 8 warps in M, NT=5.
__global__ void __launch_bounds__(256) k_gemm40(
    const __half* __restrict__ A, const __half* __restrict__ Bh,
    float* __restrict__ Out, int n)
{
    constexpr int NT = ODIM / 8;
    constexpr int BS = 136;
    __shared__ __half sB[ODIM * BS];

    int tid = threadIdx.x, wid = tid >> 5, lane = tid & 31;
    int grp = lane >> 2;
    int qid = lane & 3;
    int rowA = blockIdx.x * 128 + wid * 16 + grp;
    int rowB = rowA + 8;
    bool okA = rowA < n, okB = rowB < n;

    for (int i = tid; i < ODIM * 16; i += 256) {
        int r = i >> 4, ck = i & 15;
        *(int4*)&sB[r * BS + ck * 8] = *(const int4*)&Bh[(size_t)r * 128 + ck * 8];
    }
    __syncthreads();

    float acc[NT][4];
#pragma unroll
    for (int t = 0; t < NT; t++)
#pragma unroll
        for (int j = 0; j < 4; j++) acc[t][j] = 0.f;

    const size_t offA = (size_t)rowA * 128 + qid * 2;
    const size_t offB = (size_t)rowB * 128 + qid * 2;

#pragma unroll
    for (int k0 = 0; k0 < 128; k0 += 16) {
        uint32_t a0 = 0, a1 = 0, a2 = 0, a3 = 0;
        if (okA) {
            a0 = *(const uint32_t*)&A[offA + k0];
            a2 = *(const uint32_t*)&A[offA + k0 + 8];
        }
        if (okB) {
            a1 = *(const uint32_t*)&A[offB + k0];
            a3 = *(const uint32_t*)&A[offB + k0 + 8];
        }
#pragma unroll
        for (int t = 0; t < NT; t++) {
            const __half* bp = &sB[(t * 8 + grp) * BS + k0 + qid * 2];
            uint32_t b0 = *(const uint32_t*)bp;
            uint32_t b1 = *(const uint32_t*)(bp + 8);
            mma_f16(acc[t], a0, a1, a2, a3, b0, b1);
        }
    }

#pragma unroll
    for (int t = 0; t < NT; t++) {
        int col = t * 8 + qid * 2;
        if (okA) *(float2*)&Out[(size_t)rowA * ODIM + col] = make_float2(acc[t][0], acc[t][1]);
        if (okB) *(float2*)&Out[(size_t)rowB * ODIM + col] = make_float2(acc[t][2], acc[t][3]);
    }
}

// ======================= aggregation (128-wide) -> fp16 =======================
__global__ void __launch_bounds__(256) k_agg128(
    const float* __restrict__ Hx, const float* __restrict__ b,
    __half* __restrict__ Oh, int n)
{
    int gw = (blockIdx.x * blockDim.x + threadIdx.x) >> 5;
    int lane = threadIdx.x & 31;
    if (gw >= n) return;

    float di = g_dinv[gw];
    float sw = di * di;
    float4 acc = *(const float4*)&Hx[(size_t)gw * 128 + lane * 4];
    acc.x *= sw; acc.y *= sw; acc.z *= sw; acc.w *= sw;

    int beg = g_rowptr[gw];
    int m = g_cnt[gw];
    int e = 0;
    for (; e + 3 < m; e += 4) {
        int s0 = __ldg(&g_csrc[beg + e]);
        int s1 = __ldg(&g_csrc[beg + e + 1]);
        int s2 = __ldg(&g_csrc[beg + e + 2]);
        int s3 = __ldg(&g_csrc[beg + e + 3]);
        float w0 = __ldg(&g_cnorm[beg + e]);
        float w1 = __ldg(&g_cnorm[beg + e + 1]);
        float w2 = __ldg(&g_cnorm[beg + e + 2]);
        float w3 = __ldg(&g_cnorm[beg + e + 3]);
        float4 v0 = *(const float4*)&Hx[(size_t)s0 * 128 + lane * 4];
        float4 v1 = *(const float4*)&Hx[(size_t)s1 * 128 + lane * 4];
        float4 v2 = *(const float4*)&Hx[(size_t)s2 * 128 + lane * 4];
        float4 v3 = *(const float4*)&Hx[(size_t)s3 * 128 + lane * 4];
        acc.x += w0 * v0.x + w1 * v1.x + w2 * v2.x + w3 * v3.x;
        acc.y += w0 * v0.y + w1 * v1.y + w2 * v2.y + w3 * v3.y;
        acc.z += w0 * v0.z + w1 * v1.z + w2 * v2.z + w3 * v3.z;
        acc.w += w0 * v0.w + w1 * v1.w + w2 * v2.w + w3 * v3.w;
    }
    for (; e < m; e++) {
        int s0 = __ldg(&g_csrc[beg + e]);
        float w0 = __ldg(&g_cnorm[beg + e]);
        float4 v0 = *(const float4*)&Hx[(size_t)s0 * 128 + lane * 4];
        acc.x += w0 * v0.x; acc.y += w0 * v0.y;
        acc.z += w0 * v0.z; acc.w += w0 * v0.w;
    }

    float4 bb = *(const float4*)&b[lane * 4];
    acc.x = fmaxf(acc.x + bb.x, 0.f);
    acc.y = fmaxf(acc.y + bb.y, 0.f);
    acc.z = fmaxf(acc.z + bb.z, 0.f);
    acc.w = fmaxf(acc.w + bb.w, 0.f);

    __half2* ph = (__half2*)&Oh[(size_t)gw * 128 + lane * 4];
    ph[0] = __halves2half2(__float2half_rn(acc.x), __float2half_rn(acc.y));
    ph[1] = __halves2half2(__float2half_rn(acc.z), __float2half_rn(acc.w));
}

// ======================= aggregation (40-wide) + bias + ReLU + log_softmax =======================
__global__ void __launch_bounds__(256) k_agg40(
    const float* __restrict__ H3, const float* __restrict__ b2,
    float* __restrict__ O, int n)
{
    int gw = (blockIdx.x * blockDim.x + threadIdx.x) >> 5;
    int lane = threadIdx.x & 31;
    if (gw >= n) return;

    float di = g_dinv[gw];
    float sw = di * di;
    const float* hr = &H3[(size_t)gw * ODIM];
    float a1 = sw * hr[lane];
    float a2 = (lane < 8) ? sw * hr[32 + lane] : 0.f;

    int beg = g_rowptr[gw];
    int m = g_cnt[gw];
    int e = 0;
    for (; e + 1 < m; e += 2) {
        int s0 = __ldg(&g_csrc[beg + e]);
        int s1 = __ldg(&g_csrc[beg + e + 1]);
        float w0 = __ldg(&g_cnorm[beg + e]);
        float w1 = __ldg(&g_cnorm[beg + e + 1]);
        const float* r0 = &H3[(size_t)s0 * ODIM];
        const float* r1 = &H3[(size_t)s1 * ODIM];
        a1 += w0 * r0[lane] + w1 * r1[lane];
        if (lane < 8) a2 += w0 * r0[32 + lane] + w1 * r1[32 + lane];
    }
    if (e < m) {
        int s = __ldg(&g_csrc[beg + e]);
        float w = __ldg(&g_cnorm[beg + e]);
        const float* sr = &H3[(size_t)s * ODIM];
        a1 += w * sr[lane];
        if (lane < 8) a2 += w * sr[32 + lane];
    }

    a1 = fmaxf(a1 + b2[lane], 0.f);
    if (lane < 8) a2 = fmaxf(a2 + b2[32 + lane], 0.f);

    float mx = fmaxf(a1, (lane < 8) ? a2 : -1e30f);
#pragma unroll
    for (int off = 16; off > 0; off >>= 1)
        mx = fmaxf(mx, __shfl_xor_sync(0xFFFFFFFFu, mx, off));

    float s = expf(a1 - mx) + ((lane < 8) ? expf(a2 - mx) : 0.f);
#pragma unroll
    for (int off = 16; off > 0; off >>= 1)
        s += __shfl_xor_sync(0xFFFFFFFFu, s, off);

    float l = mx + logf(s);
    O[(size_t)gw * ODIM + lane] = a1 - l;
    if (lane < 8) O[(size_t)gw * ODIM + 32 + lane] = a2 - l;
}

// ======================= launch =======================
extern "C" void kernel_launch(void* const* d_in, const int* in_sizes, int n_in,
                              void* d_out, int out_size)
{
    const float* x  = (const float*)d_in[0];
    const void*  ei = d_in[1];
    const float* W0 = (const float*)d_in[2];
    const float* b0 = (const float*)d_in[3];
    const float* W1 = (const float*)d_in[4];
    const float* b1 = (const float*)d_in[5];
    const float* W2 = (const float*)d_in[6];
    const float* b2 = (const float*)d_in[7];
    float* out = (float*)d_out;

    int N = in_sizes[0] / HD;
    int E = in_sizes[1] / 2;

    float* hP;
    __half *xhiP, *ahiP, *w0h, *w1h, *w2h;
    cudaGetSymbolAddress((void**)&hP, g_h);
    cudaGetSymbolAddress((void**)&xhiP, g_xhi);
    cudaGetSymbolAddress((void**)&ahiP, g_ahi);
    cudaGetSymbolAddress((void**)&w0h, g_w0h);
    cudaGetSymbolAddress((void**)&w1h, g_w1h);
    cudaGetSymbolAddress((void**)&w2h, g_w2h);

    int tb = 256;
    int nbN = (N + tb - 1) / tb;
    int nbE = (E + tb - 1) / tb;
    int nbWarp = (N * 32 + tb - 1) / tb;
    int nbG64 = (N + 63) / 64;
    int nbG128 = (N + 127) / 128;
    int total4 = N * HD / 4;
    int nbPrep = (total4 + 32768 + ODIM * 128 + tb - 1) / tb;

    // idx0: prep
    k_prep<<<nbPrep, tb>>>(x, W0, W1, W2, total4);
    // idx1: init (+dtype detect)
    k_init<<<nbN, tb>>>(ei, N);
    // idx2: hist
    k_hist<<<nbE, tb>>>(ei, E);
    // idx3: layer-1 GEMM (ncu captures this slot)
    k_gemm128<<<nbG64, 256>>>(xhiP, w0h, hP, N);
    // idx4: rowptr
    k_rowptr<<<nbN, tb>>>(N);
    // idx5: fill
    k_fill<<<nbE, tb>>>(ei, E);
    // idx6: layer-1 aggregation
    k_agg128<<<nbWarp, tb>>>(hP, b0, ahiP, N);
    // layer 2
    k_gemm128<<<nbG64, 256>>>(ahiP, w1h, hP, N);
    k_agg128<<<nbWarp, tb>>>(hP, b1, ahiP, N);
    // layer 3
    k_gemm40<<<nbG128, 256>>>(ahiP, w2h, hP, N);
    k_agg40<<<nbWarp, tb>>>(hP, b2, out, N);
}

// round 8
// speedup vs baseline: 1.8681x; 1.0797x over previous
#include <cuda_runtime.h>
#include <cuda_fp16.h>
#include <cstdint>

#define NN 50000
#define EE 800000
#define HD 128
#define ODIM 40

// ---------------- scratch (static __device__, no allocations) ----------------
__device__ __align__(16) __half g_hh[NN * HD];   // GEMM outputs fp16 (40-wide reuse for L3)
__device__ __align__(16) __half g_x[NN * HD];    // input x fp16
__device__ __align__(16) __half g_a[NN * HD];    // post-agg activations fp16
__device__ __align__(16) __half g_w0h[HD * HD];
__device__ __align__(16) __half g_w1h[HD * HD];
__device__ __align__(16) __half g_w2h[ODIM * HD];
__device__ float g_dinv[NN];
__device__ int   g_cnt[NN];
__device__ int   g_rowptr[NN];
__device__ int   g_cursor[NN];
__device__ int2  g_edge[EE];                     // {src, __float_as_int(norm)}
__device__ int   g_total;
__device__ int   g_is64;

// ======================= edge-index dtype detection =======================
__device__ __forceinline__ int load_edge(const void* ei, int idx) {
    if (g_is64) return (int)((const long long*)ei)[idx];
    return ((const int*)ei)[idx];
}

// ======================= CSR build =======================
__global__ void k_init(const void* ei, int n) {
    int i = blockIdx.x * blockDim.x + threadIdx.x;
    if (i < n) g_cnt[i] = 0;
    if (i == 0) g_total = 0;
    if (blockIdx.x == 0) {
        __shared__ int any;
        if (threadIdx.x == 0) any = 0;
        __syncthreads();
        const int* p = (const int*)ei;
        for (int j = threadIdx.x; j < 512; j += blockDim.x)
            if (p[2 * j + 1] != 0) any = 1;
        __syncthreads();
        if (threadIdx.x == 0) g_is64 = any ? 0 : 1;
    }
}

__global__ void k_hist(const void* ei, int E) {
    int e = blockIdx.x * blockDim.x + threadIdx.x;
    if (e >= E) return;
    atomicAdd(&g_cnt[load_edge(ei, E + e)], 1);
}

// unordered segment assignment (order irrelevant: fill uses cursors, agg uses rowptr+cnt)
__global__ void k_rowptr(int n) {
    int i = blockIdx.x * blockDim.x + threadIdx.x;
    if (i >= n) return;
    int c = g_cnt[i];
    g_dinv[i] = rsqrtf((float)(c + 1));
    int pos = atomicAdd(&g_total, c);
    g_rowptr[i] = pos;
    g_cursor[i] = pos;
}

__global__ void k_fill(const void* ei, int E) {
    int e = blockIdx.x * blockDim.x + threadIdx.x;
    if (e >= E) return;
    int s = load_edge(ei, e);
    int d = load_edge(ei, E + e);
    int pos = atomicAdd(&g_cursor[d], 1);
    g_edge[pos] = make_int2(s, __float_as_int(g_dinv[s] * g_dinv[d]));
}

// ======================= prep: x -> fp16 + W transpose/quantize =======================
__global__ void k_prep(const float* __restrict__ x, const float* __restrict__ W0,
                       const float* __restrict__ W1, const float* __restrict__ W2,
                       int total4)
{
    int i = blockIdx.x * blockDim.x + threadIdx.x;
    if (i < total4) {
        float4 v = ((const float4*)x)[i];
        __half2* ph = (__half2*)&g_x[(size_t)i * 4];
        ph[0] = __halves2half2(__float2half_rn(v.x), __float2half_rn(v.y));
        ph[1] = __halves2half2(__float2half_rn(v.z), __float2half_rn(v.w));
    } else {
        int j = i - total4;
        if (j < 16384) {
            g_w0h[j] = __float2half_rn(W0[(j & 127) * 128 + (j >> 7)]);
        } else if (j < 32768) {
            int k = j - 16384;
            g_w1h[k] = __float2half_rn(W1[(k & 127) * 128 + (k >> 7)]);
        } else if (j < 32768 + ODIM * 128) {
            int k = j - 32768;
            int nn = k >> 7, kk = k & 127;
            g_w2h[k] = __float2half_rn(W2[kk * ODIM + nn]);
        }
    }
}

// ======================= mma.sync fp16 GEMM =======================
__device__ __forceinline__ void mma_f16(float* c, uint32_t a0, uint32_t a1,
                                        uint32_t a2, uint32_t a3,
                                        uint32_t b0, uint32_t b1) {
    asm volatile(
        "mma.sync.aligned.m16n8k16.row.col.f32.f16.f16.f32 "
        "{%0,%1,%2,%3}, {%4,%5,%6,%7}, {%8,%9}, {%0,%1,%2,%3};"
        : "+f"(c[0]), "+f"(c[1]), "+f"(c[2]), "+f"(c[3])
        : "r"(a0), "r"(a1), "r"(a2), "r"(a3), "r"(b0), "r"(b1));
}

// [n,128] @ W[K=128,128] -> [n,128] fp16 (fp32 accum).
// CTA tile 64 x 128, 8 warps (4 M x 2 N), warp tile 16 x 64, NT=8.
__global__ void __launch_bounds__(256) k_gemm128(
    const __half* __restrict__ A, const __half* __restrict__ Bh,
    __half* __restrict__ Out, int n)
{
    constexpr int NT = 8;
    constexpr int BS = 136;
    __shared__ __half sB[HD * BS];

    int tid = threadIdx.x, wid = tid >> 5, lane = tid & 31;
    int widM = wid & 3, widN = wid >> 2;
    int grp = lane >> 2;
    int qid = lane & 3;
    int rowA = blockIdx.x * 64 + widM * 16 + grp;
    int rowB = rowA + 8;
    bool okA = rowA < n, okB = rowB < n;
    int ncol0 = widN * 64;

#pragma unroll
    for (int it = 0; it < 8; it++) {
        int i = it * 256 + tid;
        int r = i >> 4, ck = i & 15;
        *(int4*)&sB[r * BS + ck * 8] = *(const int4*)&Bh[(size_t)r * 128 + ck * 8];
    }
    __syncthreads();

    float acc[NT][4];
#pragma unroll
    for (int t = 0; t < NT; t++)
#pragma unroll
        for (int j = 0; j < 4; j++) acc[t][j] = 0.f;

    const size_t offA = (size_t)rowA * 128 + qid * 2;
    const size_t offB = (size_t)rowB * 128 + qid * 2;

#pragma unroll
    for (int k0 = 0; k0 < 128; k0 += 16) {
        uint32_t a0 = 0, a1 = 0, a2 = 0, a3 = 0;
        if (okA) {
            a0 = *(const uint32_t*)&A[offA + k0];
            a2 = *(const uint32_t*)&A[offA + k0 + 8];
        }
        if (okB) {
            a1 = *(const uint32_t*)&A[offB + k0];
            a3 = *(const uint32_t*)&A[offB + k0 + 8];
        }
#pragma unroll
        for (int t = 0; t < NT; t++) {
            const __half* bp = &sB[(ncol0 + t * 8 + grp) * BS + k0 + qid * 2];
            uint32_t b0 = *(const uint32_t*)bp;
            uint32_t b1 = *(const uint32_t*)(bp + 8);
            mma_f16(acc[t], a0, a1, a2, a3, b0, b1);
        }
    }

#pragma unroll
    for (int t = 0; t < NT; t++) {
        int col = ncol0 + t * 8 + qid * 2;
        if (okA) *(__half2*)&Out[(size_t)rowA * 128 + col] = __floats2half2_rn(acc[t][0], acc[t][1]);
        if (okB) *(__half2*)&Out[(size_t)rowB * 128 + col] = __floats2half2_rn(acc[t][2], acc[t][3]);
    }
}

// [n,128] @ W2[K=128,40] -> [n,40] fp16. CTA tile 128 x 40, 8 warps in M, NT=5.
__global__ void __launch_bounds__(256) k_gemm40(
    const __half* __restrict__ A, const __half* __restrict__ Bh,
    __half* __restrict__ Out, int n)
{
    constexpr int NT = ODIM / 8;
    constexpr int BS = 136;
    __shared__ __half sB[ODIM * BS];

    int tid = threadIdx.x, wid = tid >> 5, lane = tid & 31;
    int grp = lane >> 2;
    int qid = lane & 3;
    int rowA = blockIdx.x * 128 + wid * 16 + grp;
    int rowB = rowA + 8;
    bool okA = rowA < n, okB = rowB < n;

    for (int i = tid; i < ODIM * 16; i += 256) {
        int r = i >> 4, ck = i & 15;
        *(int4*)&sB[r * BS + ck * 8] = *(const int4*)&Bh[(size_t)r * 128 + ck * 8];
    }
    __syncthreads();

    float acc[NT][4];
#pragma unroll
    for (int t = 0; t < NT; t++)
#pragma unroll
        for (int j = 0; j < 4; j++) acc[t][j] = 0.f;

    const size_t offA = (size_t)rowA * 128 + qid * 2;
    const size_t offB = (size_t)rowB * 128 + qid * 2;

#pragma unroll
    for (int k0 = 0; k0 < 128; k0 += 16) {
        uint32_t a0 = 0, a1 = 0, a2 = 0, a3 = 0;
        if (okA) {
            a0 = *(const uint32_t*)&A[offA + k0];
            a2 = *(const uint32_t*)&A[offA + k0 + 8];
        }
        if (okB) {
            a1 = *(const uint32_t*)&A[offB + k0];
            a3 = *(const uint32_t*)&A[offB + k0 + 8];
        }
#pragma unroll
        for (int t = 0; t < NT; t++) {
            const __half* bp = &sB[(t * 8 + grp) * BS + k0 + qid * 2];
            uint32_t b0 = *(const uint32_t*)bp;
            uint32_t b1 = *(const uint32_t*)(bp + 8);
            mma_f16(acc[t], a0, a1, a2, a3, b0, b1);
        }
    }

#pragma unroll
    for (int t = 0; t < NT; t++) {
        int col = t * 8 + qid * 2;
        if (okA) *(__half2*)&Out[(size_t)rowA * ODIM + col] = __floats2half2_rn(acc[t][0], acc[t][1]);
        if (okB) *(__half2*)&Out[(size_t)rowB * ODIM + col] = __floats2half2_rn(acc[t][2], acc[t][3]);
    }
}

// ======================= aggregation (128-wide, fp16 gather) -> fp16 =======================
__device__ __forceinline__ float4 ldrow128(const __half* __restrict__ H, int row, int lane) {
    uint2 u = *(const uint2*)&H[(size_t)row * 128 + lane * 4];
    float2 fa = __half22float2(*(__half2*)&u.x);
    float2 fb = __half22float2(*(__half2*)&u.y);
    return make_float4(fa.x, fa.y, fb.x, fb.y);
}

__global__ void __launch_bounds__(256) k_agg128(
    const __half* __restrict__ Hh, const float* __restrict__ b,
    __half* __restrict__ Oh, int n)
{
    int gw = (blockIdx.x * blockDim.x + threadIdx.x) >> 5;
    int lane = threadIdx.x & 31;
    if (gw >= n) return;

    float di = g_dinv[gw];
    float sw = di * di;
    float4 v = ldrow128(Hh, gw, lane);
    float4 acc = make_float4(v.x * sw, v.y * sw, v.z * sw, v.w * sw);

    int beg = g_rowptr[gw];
    int m = g_cnt[gw];
    int e = 0;
    for (; e + 3 < m; e += 4) {
        int2 E0 = __ldg(&g_edge[beg + e]);
        int2 E1 = __ldg(&g_edge[beg + e + 1]);
        int2 E2 = __ldg(&g_edge[beg + e + 2]);
        int2 E3 = __ldg(&g_edge[beg + e + 3]);
        float4 v0 = ldrow128(Hh, E0.x, lane);
        float4 v1 = ldrow128(Hh, E1.x, lane);
        float4 v2 = ldrow128(Hh, E2.x, lane);
        float4 v3 = ldrow128(Hh, E3.x, lane);
        float w0 = __int_as_float(E0.y), w1 = __int_as_float(E1.y);
        float w2 = __int_as_float(E2.y), w3 = __int_as_float(E3.y);
        acc.x += w0 * v0.x + w1 * v1.x + w2 * v2.x + w3 * v3.x;
        acc.y += w0 * v0.y + w1 * v1.y + w2 * v2.y + w3 * v3.y;
        acc.z += w0 * v0.z + w1 * v1.z + w2 * v2.z + w3 * v3.z;
        acc.w += w0 * v0.w + w1 * v1.w + w2 * v2.w + w3 * v3.w;
    }
    for (; e < m; e++) {
        int2 E0 = __ldg(&g_edge[beg + e]);
        float w0 = __int_as_float(E0.y);
        float4 v0 = ldrow128(Hh, E0.x, lane);
        acc.x += w0 * v0.x; acc.y += w0 * v0.y;
        acc.z += w0 * v0.z; acc.w += w0 * v0.w;
    }

    float4 bb = *(const float4*)&b[lane * 4];
    acc.x = fmaxf(acc.x + bb.x, 0.f);
    acc.y = fmaxf(acc.y + bb.y, 0.f);
    acc.z = fmaxf(acc.z + bb.z, 0.f);
    acc.w = fmaxf(acc.w + bb.w, 0.f);

    __half2* ph = (__half2*)&Oh[(size_t)gw * 128 + lane * 4];
    ph[0] = __floats2half2_rn(acc.x, acc.y);
    ph[1] = __floats2half2_rn(acc.z, acc.w);
}

// ======================= aggregation (40-wide, fp16 gather) + bias + ReLU + log_softmax =======================
__global__ void __launch_bounds__(256) k_agg40(
    const __half* __restrict__ H3, const float* __restrict__ b2,
    float* __restrict__ O, int n)
{
    int gw = (blockIdx.x * blockDim.x + threadIdx.x) >> 5;
    int lane = threadIdx.x & 31;
    if (gw >= n) return;

    float di = g_dinv[gw];
    float sw = di * di;
    const __half* hr = &H3[(size_t)gw * ODIM];
    float a1 = sw * __half2float(hr[lane]);
    float a2 = (lane < 8) ? sw * __half2float(hr[32 + lane]) : 0.f;

    int beg = g_rowptr[gw];
    int m = g_cnt[gw];
    int e = 0;
    for (; e + 1 < m; e += 2) {
        int2 E0 = __ldg(&g_edge[beg + e]);
        int2 E1 = __ldg(&g_edge[beg + e + 1]);
        float w0 = __int_as_float(E0.y), w1 = __int_as_float(E1.y);
        const __half* r0 = &H3[(size_t)E0.x * ODIM];
        const __half* r1 = &H3[(size_t)E1.x * ODIM];
        a1 += w0 * __half2float(r0[lane]) + w1 * __half2float(r1[lane]);
        if (lane < 8)
            a2 += w0 * __half2float(r0[32 + lane]) + w1 * __half2float(r1[32 + lane]);
    }
    if (e < m) {
        int2 E0 = __ldg(&g_edge[beg + e]);
        float w = __int_as_float(E0.y);
        const __half* sr = &H3[(size_t)E0.x * ODIM];
        a1 += w * __half2float(sr[lane]);
        if (lane < 8) a2 += w * __half2float(sr[32 + lane]);
    }

    a1 = fmaxf(a1 + b2[lane], 0.f);
    if (lane < 8) a2 = fmaxf(a2 + b2[32 + lane], 0.f);

    float mx = fmaxf(a1, (lane < 8) ? a2 : -1e30f);
#pragma unroll
    for (int off = 16; off > 0; off >>= 1)
        mx = fmaxf(mx, __shfl_xor_sync(0xFFFFFFFFu, mx, off));

    float s = expf(a1 - mx) + ((lane < 8) ? expf(a2 - mx) : 0.f);
#pragma unroll
    for (int off = 16; off > 0; off >>= 1)
        s += __shfl_xor_sync(0xFFFFFFFFu, s, off);

    float l = mx + logf(s);
    O[(size_t)gw * ODIM + lane] = a1 - l;
    if (lane < 8) O[(size_t)gw * ODIM + 32 + lane] = a2 - l;
}

// ======================= launch =======================
extern "C" void kernel_launch(void* const* d_in, const int* in_sizes, int n_in,
                              void* d_out, int out_size)
{
    const float* x  = (const float*)d_in[0];
    const void*  ei = d_in[1];
    const float* W0 = (const float*)d_in[2];
    const float* b0 = (const float*)d_in[3];
    const float* W1 = (const float*)d_in[4];
    const float* b1 = (const float*)d_in[5];
    const float* W2 = (const float*)d_in[6];
    const float* b2 = (const float*)d_in[7];
    float* out = (float*)d_out;

    int N = in_sizes[0] / HD;
    int E = in_sizes[1] / 2;

    __half *hhP, *xP, *aP, *w0h, *w1h, *w2h;
    cudaGetSymbolAddress((void**)&hhP, g_hh);
    cudaGetSymbolAddress((void**)&xP, g_x);
    cudaGetSymbolAddress((void**)&aP, g_a);
    cudaGetSymbolAddress((void**)&w0h, g_w0h);
    cudaGetSymbolAddress((void**)&w1h, g_w1h);
    cudaGetSymbolAddress((void**)&w2h, g_w2h);

    int tb = 256;
    int nbN = (N + tb - 1) / tb;
    int nbE = (E + tb - 1) / tb;
    int nbWarp = (N * 32 + tb - 1) / tb;
    int nbG64 = (N + 63) / 64;
    int nbG128 = (N + 127) / 128;
    int total4 = N * HD / 4;
    int nbPrep = (total4 + 32768 + ODIM * 128 + tb - 1) / tb;

    // idx0..3: CSR build (k_fill at capture slot 3)
    k_init<<<nbN, tb>>>(ei, N);
    k_hist<<<nbE, tb>>>(ei, E);
    k_rowptr<<<nbN, tb>>>(N);
    k_fill<<<nbE, tb>>>(ei, E);
    // idx4: prep
    k_prep<<<nbPrep, tb>>>(x, W0, W1, W2, total4);
    // layer 1
    k_gemm128<<<nbG64, 256>>>(xP, w0h, hhP, N);
    k_agg128<<<nbWarp, tb>>>(hhP, b0, aP, N);
    // layer 2
    k_gemm128<<<nbG64, 256>>>(aP, w1h, hhP, N);
    k_agg128<<<nbWarp, tb>>>(hhP, b1, aP, N);
    // layer 3
    k_gemm40<<<nbG128, 256>>>(aP, w2h, hhP, N);
    k_agg40<<<nbWarp, tb>>>(hhP, b2, out, N);
}